// round 2
// baseline (speedup 1.0000x reference)
#include <cuda_runtime.h>
#include <cstdint>

#define NN 100000
#define IND 256
#define HD 128

// Scratch (static device globals — allocation-free per harness rules)
__device__ float g_deg[NN];
__device__ float g_dinv[NN];
__device__ float g_xws[(size_t)NN * HD];   // (x@W)*dinv  (read side of scatter)
__device__ float g_acc[(size_t)NN * HD];   // accumulator, init = xws (self loop)
__device__ float g_h1[(size_t)NN * HD];    // relu output of conv1

// ---------------------------------------------------------------------------
// Degree / normalization: deg[i] = 1 (self loop) + #(dst == i); dinv = rsqrt
// ---------------------------------------------------------------------------
__global__ void deg_init_kernel() {
    int i = blockIdx.x * blockDim.x + threadIdx.x;
    if (i < NN) g_deg[i] = 1.0f;
}

__global__ void deg_count_kernel(const int* __restrict__ dst, int E) {
    int i = blockIdx.x * blockDim.x + threadIdx.x;
    if (i < E) atomicAdd(&g_deg[dst[i]], 1.0f);
}

__global__ void dinv_kernel() {
    int i = blockIdx.x * blockDim.x + threadIdx.x;
    if (i < NN) g_dinv[i] = rsqrtf(g_deg[i]);
}

// ---------------------------------------------------------------------------
// SGEMM: C = A[M x K] @ B[K x 128], epilogue scales row by dinv[row] and
// writes BOTH g_xws and g_acc (acc starts at the self-loop contribution).
// BM=128, BN=128, BK=8, 256 threads, 8x8 register tile per thread.
// ---------------------------------------------------------------------------
template<int K, bool USE_H1>
__global__ void __launch_bounds__(256) sgemm_kernel(const float* __restrict__ A,
                                                    const float* __restrict__ B,
                                                    int M)
{
    constexpr int BM = 128, BN = 128, BK = 8;
    __shared__ float As[BK][BM];
    __shared__ float Bs[BK][BN];
    const float* Ap = USE_H1 ? (const float*)g_h1 : A;

    int tid  = threadIdx.x;
    int row0 = blockIdx.x * BM;
    int tx   = tid & 15;         // 0..15 -> 8 output cols each
    int ty   = tid >> 4;         // 0..15 -> 8 output rows each

    int aRow = tid >> 1;         // 0..127
    int aCol = (tid & 1) << 2;   // 0 or 4
    int bRow = tid >> 5;         // 0..7
    int bCol = (tid & 31) << 2;  // 0..124

    float acc[8][8];
    #pragma unroll
    for (int i = 0; i < 8; i++)
        #pragma unroll
        for (int j = 0; j < 8; j++) acc[i][j] = 0.0f;

    for (int k0 = 0; k0 < K; k0 += BK) {
        float4 av = make_float4(0.f, 0.f, 0.f, 0.f);
        if (row0 + aRow < M)
            av = *(const float4*)(Ap + (size_t)(row0 + aRow) * K + (k0 + aCol));
        As[aCol + 0][aRow] = av.x;
        As[aCol + 1][aRow] = av.y;
        As[aCol + 2][aRow] = av.z;
        As[aCol + 3][aRow] = av.w;
        *(float4*)&Bs[bRow][bCol] = *(const float4*)(B + (size_t)(k0 + bRow) * BN + bCol);
        __syncthreads();
        #pragma unroll
        for (int k = 0; k < BK; k++) {
            float ra[8], rb[8];
            #pragma unroll
            for (int i = 0; i < 8; i++) ra[i] = As[k][ty * 8 + i];
            #pragma unroll
            for (int j = 0; j < 8; j++) rb[j] = Bs[k][tx * 8 + j];
            #pragma unroll
            for (int i = 0; i < 8; i++)
                #pragma unroll
                for (int j = 0; j < 8; j++)
                    acc[i][j] = fmaf(ra[i], rb[j], acc[i][j]);
        }
        __syncthreads();
    }

    #pragma unroll
    for (int i = 0; i < 8; i++) {
        int r = row0 + ty * 8 + i;
        if (r < M) {
            float s = g_dinv[r];
            #pragma unroll
            for (int h = 0; h < 2; h++) {
                float4 o;
                o.x = acc[i][h * 4 + 0] * s;
                o.y = acc[i][h * 4 + 1] * s;
                o.z = acc[i][h * 4 + 2] * s;
                o.w = acc[i][h * 4 + 3] * s;
                size_t off = (size_t)r * HD + tx * 8 + h * 4;
                *(float4*)(g_xws + off) = o;
                *(float4*)(g_acc + off) = o;   // self-loop init
            }
        }
    }
}

// ---------------------------------------------------------------------------
// Edge scatter: one warp per edge; lane L handles feature chunk [4L, 4L+4).
// acc[dst] += xws[src]   via red.global.add.v4.f32 (L2-side vector reduction)
// ---------------------------------------------------------------------------
__global__ void __launch_bounds__(256) scatter_kernel(const int* __restrict__ src,
                                                      const int* __restrict__ dst,
                                                      int E)
{
    int w = (int)((blockIdx.x * 256u + threadIdx.x) >> 5);
    if (w >= E) return;
    int lane = threadIdx.x & 31;
    int s = __ldg(&src[w]);
    int d = __ldg(&dst[w]);
    const float4 v = *(const float4*)(g_xws + (size_t)s * HD + lane * 4);
    float* p = g_acc + (size_t)d * HD + lane * 4;
    asm volatile("red.global.add.v4.f32 [%0], {%1,%2,%3,%4};"
                 :: "l"(p), "f"(v.x), "f"(v.y), "f"(v.z), "f"(v.w)
                 : "memory");
}

// ---------------------------------------------------------------------------
// h1 = relu(dinv[row] * acc + b1)   (vectorized elementwise, float4 per thread)
// ---------------------------------------------------------------------------
__global__ void relu_finalize_kernel(const float* __restrict__ b1) {
    int i = blockIdx.x * blockDim.x + threadIdx.x;       // float4 index
    if (i >= NN * HD / 4) return;
    int row = i >> 5;       // 32 float4 per row
    int c4  = i & 31;
    float s = g_dinv[row];
    float4 a = ((const float4*)g_acc)[i];
    float4 b = ((const float4*)b1)[c4];
    float4 h;
    h.x = fmaxf(fmaf(a.x, s, b.x), 0.f);
    h.y = fmaxf(fmaf(a.y, s, b.y), 0.f);
    h.z = fmaxf(fmaf(a.z, s, b.z), 0.f);
    h.w = fmaxf(fmaf(a.w, s, b.w), 0.f);
    ((float4*)g_h1)[i] = h;
}

// ---------------------------------------------------------------------------
// Output: one warp per node.
//   h2 = relu(dinv*acc2 + b2); h2a = alpha*h2 + (1-alpha)*h1
//   out = 0.5*(h1@Wc + bc) + 0.5*(h2a@Wf + bf)
// ---------------------------------------------------------------------------
__global__ void __launch_bounds__(256) output_kernel(const float* __restrict__ hnode,
                                                     const float* __restrict__ b2,
                                                     const float* __restrict__ Wc,
                                                     const float* __restrict__ bc,
                                                     const float* __restrict__ Wf,
                                                     const float* __restrict__ bf,
                                                     float* __restrict__ out)
{
    int w = (int)((blockIdx.x * 256u + threadIdx.x) >> 5);
    if (w >= NN) return;
    int lane = threadIdx.x & 31;
    float s     = g_dinv[w];
    float alpha = hnode[w];
    size_t base = (size_t)w * HD + lane * 4;
    float4 h1v = *(const float4*)(g_h1 + base);
    float4 av  = *(const float4*)(g_acc + base);
    float4 bv  = ((const float4*)b2)[lane];

    float4 h2;
    h2.x = fmaxf(fmaf(av.x, s, bv.x), 0.f);
    h2.y = fmaxf(fmaf(av.y, s, bv.y), 0.f);
    h2.z = fmaxf(fmaf(av.z, s, bv.z), 0.f);
    h2.w = fmaxf(fmaf(av.w, s, bv.w), 0.f);

    float beta = 1.0f - alpha;
    float4 ha;
    ha.x = alpha * h2.x + beta * h1v.x;
    ha.y = alpha * h2.y + beta * h1v.y;
    ha.z = alpha * h2.z + beta * h1v.z;
    ha.w = alpha * h2.w + beta * h1v.w;

    // Wc/Wf are [128 x 2] row-major; lane covers rows 4L..4L+3 => 8 floats
    float4 wc0 = *(const float4*)(Wc + lane * 8);
    float4 wc1 = *(const float4*)(Wc + lane * 8 + 4);
    float4 wf0 = *(const float4*)(Wf + lane * 8);
    float4 wf1 = *(const float4*)(Wf + lane * 8 + 4);

    float c0 = h1v.x * wc0.x + h1v.y * wc0.z + h1v.z * wc1.x + h1v.w * wc1.z;
    float c1 = h1v.x * wc0.y + h1v.y * wc0.w + h1v.z * wc1.y + h1v.w * wc1.w;
    float f0 = ha.x * wf0.x + ha.y * wf0.z + ha.z * wf1.x + ha.w * wf1.z;
    float f1 = ha.x * wf0.y + ha.y * wf0.w + ha.z * wf1.y + ha.w * wf1.w;

    #pragma unroll
    for (int off = 16; off > 0; off >>= 1) {
        c0 += __shfl_xor_sync(0xFFFFFFFFu, c0, off);
        c1 += __shfl_xor_sync(0xFFFFFFFFu, c1, off);
        f0 += __shfl_xor_sync(0xFFFFFFFFu, f0, off);
        f1 += __shfl_xor_sync(0xFFFFFFFFu, f1, off);
    }
    if (lane == 0) {
        out[2 * (size_t)w + 0] = 0.5f * (c0 + bc[0]) + 0.5f * (f0 + bf[0]);
        out[2 * (size_t)w + 1] = 0.5f * (c1 + bc[1]) + 0.5f * (f1 + bf[1]);
    }
}

// ---------------------------------------------------------------------------
extern "C" void kernel_launch(void* const* d_in, const int* in_sizes, int n_in,
                              void* d_out, int out_size)
{
    const float* x     = (const float*)d_in[0];
    const int*   ei    = (const int*)d_in[1];     // int32! (jax x64 disabled)
    const float* hnode = (const float*)d_in[2];
    const float* W1    = (const float*)d_in[3];
    const float* b1    = (const float*)d_in[4];
    const float* W2    = (const float*)d_in[5];
    const float* b2    = (const float*)d_in[6];
    const float* Wc    = (const float*)d_in[7];
    const float* bc    = (const float*)d_in[8];
    const float* Wf    = (const float*)d_in[9];
    const float* bf    = (const float*)d_in[10];
    float* out = (float*)d_out;

    int E = in_sizes[1] / 2;
    const int* src = ei;
    const int* dst = ei + E;

    // Degree + normalization
    deg_init_kernel<<<(NN + 255) / 256, 256>>>();
    deg_count_kernel<<<(E + 255) / 256, 256>>>(dst, E);
    dinv_kernel<<<(NN + 255) / 256, 256>>>();

    // Conv1: xws = (x@W1)*dinv ; acc = xws ; acc[d] += xws[s] ; h1 = relu(dinv*acc + b1)
    sgemm_kernel<IND, false><<<(NN + 127) / 128, 256>>>(x, W1, NN);
    scatter_kernel<<<((size_t)E * 32 + 255) / 256, 256>>>(src, dst, E);
    relu_finalize_kernel<<<(NN * HD / 4 + 255) / 256, 256>>>(b1);

    // Conv2 (reuses xws/acc buffers)
    sgemm_kernel<HD, true><<<(NN + 127) / 128, 256>>>(nullptr, W2, NN);
    scatter_kernel<<<((size_t)E * 32 + 255) / 256, 256>>>(src, dst, E);

    // Fused h2/blend/heads/output
    output_kernel<<<((size_t)NN * 32 + 255) / 256, 256>>>(hnode, b2, Wc, bc, Wf, bf, out);
}

// round 3
// speedup vs baseline: 1.7131x; 1.7131x over previous
#include <cuda_runtime.h>
#include <cstdint>

#define NN 100000
#define IND 256
#define HD 128
#define PAD 128          // max in-degree capacity per node (Poisson(16) -> max ~45)

// Scratch (static device globals — allocation-free per harness rules)
__device__ int   g_cnt[NN];                     // in-degree (excl self loop)
__device__ float g_dinv[NN];
__device__ int   g_csr[(size_t)NN * PAD];       // src lists bucketed by dst
__device__ float g_xws[(size_t)NN * HD];        // (A@W)*dinv  (gather source)
__device__ float g_h1[(size_t)NN * HD];         // relu output of conv1

// ---------------------------------------------------------------------------
__global__ void zero_cnt_kernel() {
    int i = blockIdx.x * blockDim.x + threadIdx.x;
    if (i < NN) g_cnt[i] = 0;
}

// Bucket edges by dst: csr[dst*PAD + pos] = src
__global__ void csr_fill_kernel(const int* __restrict__ src,
                                const int* __restrict__ dst, int E) {
    int i = blockIdx.x * blockDim.x + threadIdx.x;
    if (i >= E) return;
    int d = dst[i];
    int pos = atomicAdd(&g_cnt[d], 1);
    if (pos < PAD) g_csr[(size_t)d * PAD + pos] = src[i];
}

__global__ void dinv_kernel() {
    int i = blockIdx.x * blockDim.x + threadIdx.x;
    if (i < NN) g_dinv[i] = rsqrtf(1.0f + (float)g_cnt[i]);
}

// ---------------------------------------------------------------------------
// SGEMM: C = A[M x K] @ B[K x 128]; epilogue scales row by dinv[row] -> g_xws.
// BM=128, BN=128, BK=8, 256 threads, 8x8 register tile per thread.
// ---------------------------------------------------------------------------
template<int K, bool USE_H1>
__global__ void __launch_bounds__(256) sgemm_kernel(const float* __restrict__ A,
                                                    const float* __restrict__ B,
                                                    int M)
{
    constexpr int BM = 128, BN = 128, BK = 8;
    __shared__ float As[BK][BM];
    __shared__ float Bs[BK][BN];
    const float* Ap = USE_H1 ? (const float*)g_h1 : A;

    int tid  = threadIdx.x;
    int row0 = blockIdx.x * BM;
    int tx   = tid & 15;
    int ty   = tid >> 4;

    int aRow = tid >> 1;
    int aCol = (tid & 1) << 2;
    int bRow = tid >> 5;
    int bCol = (tid & 31) << 2;

    float acc[8][8];
    #pragma unroll
    for (int i = 0; i < 8; i++)
        #pragma unroll
        for (int j = 0; j < 8; j++) acc[i][j] = 0.0f;

    for (int k0 = 0; k0 < K; k0 += BK) {
        float4 av = make_float4(0.f, 0.f, 0.f, 0.f);
        if (row0 + aRow < M)
            av = *(const float4*)(Ap + (size_t)(row0 + aRow) * K + (k0 + aCol));
        As[aCol + 0][aRow] = av.x;
        As[aCol + 1][aRow] = av.y;
        As[aCol + 2][aRow] = av.z;
        As[aCol + 3][aRow] = av.w;
        *(float4*)&Bs[bRow][bCol] = *(const float4*)(B + (size_t)(k0 + bRow) * BN + bCol);
        __syncthreads();
        #pragma unroll
        for (int k = 0; k < BK; k++) {
            float ra[8], rb[8];
            #pragma unroll
            for (int i = 0; i < 8; i++) ra[i] = As[k][ty * 8 + i];
            #pragma unroll
            for (int j = 0; j < 8; j++) rb[j] = Bs[k][tx * 8 + j];
            #pragma unroll
            for (int i = 0; i < 8; i++)
                #pragma unroll
                for (int j = 0; j < 8; j++)
                    acc[i][j] = fmaf(ra[i], rb[j], acc[i][j]);
        }
        __syncthreads();
    }

    #pragma unroll
    for (int i = 0; i < 8; i++) {
        int r = row0 + ty * 8 + i;
        if (r < M) {
            float s = g_dinv[r];
            #pragma unroll
            for (int h = 0; h < 2; h++) {
                float4 o;
                o.x = acc[i][h * 4 + 0] * s;
                o.y = acc[i][h * 4 + 1] * s;
                o.z = acc[i][h * 4 + 2] * s;
                o.w = acc[i][h * 4 + 3] * s;
                *(float4*)(g_xws + (size_t)r * HD + tx * 8 + h * 4) = o;
            }
        }
    }
}

// ---------------------------------------------------------------------------
// agg1: warp per node. sum = xws[n] + sum_{e} xws[csr[n][e]]
//       h1 = relu(dinv[n]*sum + b1)
// Lane L owns features [4L, 4L+4).
// ---------------------------------------------------------------------------
__global__ void __launch_bounds__(256) agg1_kernel(const float* __restrict__ b1) {
    int n = (int)((blockIdx.x * 256u + threadIdx.x) >> 5);
    if (n >= NN) return;
    int lane = threadIdx.x & 31;
    int cnt = g_cnt[n];
    const int* lst = g_csr + (size_t)n * PAD;

    float4 sum = *(const float4*)(g_xws + (size_t)n * HD + lane * 4);  // self loop

    int e = 0;
    for (; e + 2 <= cnt; e += 2) {           // unroll 2 for MLP
        int s0 = __ldg(&lst[e]);
        int s1 = __ldg(&lst[e + 1]);
        float4 v0 = *(const float4*)(g_xws + (size_t)s0 * HD + lane * 4);
        float4 v1 = *(const float4*)(g_xws + (size_t)s1 * HD + lane * 4);
        sum.x += v0.x + v1.x;  sum.y += v0.y + v1.y;
        sum.z += v0.z + v1.z;  sum.w += v0.w + v1.w;
    }
    if (e < cnt) {
        int s0 = __ldg(&lst[e]);
        float4 v0 = *(const float4*)(g_xws + (size_t)s0 * HD + lane * 4);
        sum.x += v0.x;  sum.y += v0.y;  sum.z += v0.z;  sum.w += v0.w;
    }

    float s = g_dinv[n];
    float4 b = ((const float4*)b1)[lane];
    float4 h;
    h.x = fmaxf(fmaf(sum.x, s, b.x), 0.f);
    h.y = fmaxf(fmaf(sum.y, s, b.y), 0.f);
    h.z = fmaxf(fmaf(sum.z, s, b.z), 0.f);
    h.w = fmaxf(fmaf(sum.w, s, b.w), 0.f);
    *(float4*)(g_h1 + (size_t)n * HD + lane * 4) = h;
}

// ---------------------------------------------------------------------------
// agg2 + output: warp per node.
//   sum2 = xws[n] + gather;  h2 = relu(dinv*sum2 + b2)
//   h2a = alpha*h2 + (1-alpha)*h1
//   out = 0.5*(h1@Wc + bc) + 0.5*(h2a@Wf + bf)
// ---------------------------------------------------------------------------
__global__ void __launch_bounds__(256) agg2out_kernel(const float* __restrict__ hnode,
                                                      const float* __restrict__ b2,
                                                      const float* __restrict__ Wc,
                                                      const float* __restrict__ bc,
                                                      const float* __restrict__ Wf,
                                                      const float* __restrict__ bf,
                                                      float* __restrict__ out)
{
    int n = (int)((blockIdx.x * 256u + threadIdx.x) >> 5);
    if (n >= NN) return;
    int lane = threadIdx.x & 31;
    int cnt = g_cnt[n];
    const int* lst = g_csr + (size_t)n * PAD;

    float4 sum = *(const float4*)(g_xws + (size_t)n * HD + lane * 4);  // self loop

    int e = 0;
    for (; e + 2 <= cnt; e += 2) {
        int s0 = __ldg(&lst[e]);
        int s1 = __ldg(&lst[e + 1]);
        float4 v0 = *(const float4*)(g_xws + (size_t)s0 * HD + lane * 4);
        float4 v1 = *(const float4*)(g_xws + (size_t)s1 * HD + lane * 4);
        sum.x += v0.x + v1.x;  sum.y += v0.y + v1.y;
        sum.z += v0.z + v1.z;  sum.w += v0.w + v1.w;
    }
    if (e < cnt) {
        int s0 = __ldg(&lst[e]);
        float4 v0 = *(const float4*)(g_xws + (size_t)s0 * HD + lane * 4);
        sum.x += v0.x;  sum.y += v0.y;  sum.z += v0.z;  sum.w += v0.w;
    }

    float s     = g_dinv[n];
    float alpha = hnode[n];
    float beta  = 1.0f - alpha;
    float4 bv   = ((const float4*)b2)[lane];
    float4 h1v  = *(const float4*)(g_h1 + (size_t)n * HD + lane * 4);

    float4 h2, ha;
    h2.x = fmaxf(fmaf(sum.x, s, bv.x), 0.f);
    h2.y = fmaxf(fmaf(sum.y, s, bv.y), 0.f);
    h2.z = fmaxf(fmaf(sum.z, s, bv.z), 0.f);
    h2.w = fmaxf(fmaf(sum.w, s, bv.w), 0.f);
    ha.x = alpha * h2.x + beta * h1v.x;
    ha.y = alpha * h2.y + beta * h1v.y;
    ha.z = alpha * h2.z + beta * h1v.z;
    ha.w = alpha * h2.w + beta * h1v.w;

    // Wc/Wf are [128 x 2] row-major; lane covers rows 4L..4L+3 => 8 floats
    float4 wc0 = *(const float4*)(Wc + lane * 8);
    float4 wc1 = *(const float4*)(Wc + lane * 8 + 4);
    float4 wf0 = *(const float4*)(Wf + lane * 8);
    float4 wf1 = *(const float4*)(Wf + lane * 8 + 4);

    float c0 = h1v.x * wc0.x + h1v.y * wc0.z + h1v.z * wc1.x + h1v.w * wc1.z;
    float c1 = h1v.x * wc0.y + h1v.y * wc0.w + h1v.z * wc1.y + h1v.w * wc1.w;
    float f0 = ha.x * wf0.x + ha.y * wf0.z + ha.z * wf1.x + ha.w * wf1.z;
    float f1 = ha.x * wf0.y + ha.y * wf0.w + ha.z * wf1.y + ha.w * wf1.w;

    #pragma unroll
    for (int off = 16; off > 0; off >>= 1) {
        c0 += __shfl_xor_sync(0xFFFFFFFFu, c0, off);
        c1 += __shfl_xor_sync(0xFFFFFFFFu, c1, off);
        f0 += __shfl_xor_sync(0xFFFFFFFFu, f0, off);
        f1 += __shfl_xor_sync(0xFFFFFFFFu, f1, off);
    }
    if (lane == 0) {
        out[2 * (size_t)n + 0] = 0.5f * (c0 + bc[0]) + 0.5f * (f0 + bf[0]);
        out[2 * (size_t)n + 1] = 0.5f * (c1 + bc[1]) + 0.5f * (f1 + bf[1]);
    }
}

// ---------------------------------------------------------------------------
extern "C" void kernel_launch(void* const* d_in, const int* in_sizes, int n_in,
                              void* d_out, int out_size)
{
    const float* x     = (const float*)d_in[0];
    const int*   ei    = (const int*)d_in[1];     // int32 (jax x64 disabled)
    const float* hnode = (const float*)d_in[2];
    const float* W1    = (const float*)d_in[3];
    const float* b1    = (const float*)d_in[4];
    const float* W2    = (const float*)d_in[5];
    const float* b2    = (const float*)d_in[6];
    const float* Wc    = (const float*)d_in[7];
    const float* bc    = (const float*)d_in[8];
    const float* Wf    = (const float*)d_in[9];
    const float* bf    = (const float*)d_in[10];
    float* out = (float*)d_out;

    int E = in_sizes[1] / 2;
    const int* src = ei;
    const int* dst = ei + E;

    // CSR build + normalization
    zero_cnt_kernel<<<(NN + 255) / 256, 256>>>();
    csr_fill_kernel<<<(E + 255) / 256, 256>>>(src, dst, E);
    dinv_kernel<<<(NN + 255) / 256, 256>>>();

    // Conv1
    sgemm_kernel<IND, false><<<(NN + 127) / 128, 256>>>(x, W1, NN);
    agg1_kernel<<<((size_t)NN * 32 + 255) / 256, 256>>>(b1);

    // Conv2 + fused blend/heads/output
    sgemm_kernel<HD, true><<<(NN + 127) / 128, 256>>>(nullptr, W2, NN);
    agg2out_kernel<<<((size_t)NN * 32 + 255) / 256, 256>>>(hnode, b2, Wc, bc, Wf, bf, out);
}

// round 4
// speedup vs baseline: 2.9647x; 1.7306x over previous
#include <cuda_runtime.h>
#include <cstdint>

#define NN 100000
#define IND 256
#define HD 128
#define PAD 128          // max in-degree capacity per node (Poisson(16) -> max ~45)

// Scratch (static device globals — allocation-free per harness rules)
__device__ int   g_cnt[NN];                     // in-degree (excl self loop)
__device__ float g_dinv[NN];
__device__ int   g_csr[(size_t)NN * PAD];       // src lists bucketed by dst
__device__ float g_xws[(size_t)NN * HD];        // (A@W)*dinv  (gather source)
__device__ float g_h1[(size_t)NN * HD];         // relu output of conv1

// ---------------------------------------------------------------------------
__global__ void zero_cnt_kernel() {
    int i = blockIdx.x * blockDim.x + threadIdx.x;
    if (i < NN) g_cnt[i] = 0;
}

__global__ void csr_fill_kernel(const int* __restrict__ src,
                                const int* __restrict__ dst, int E) {
    int i = blockIdx.x * blockDim.x + threadIdx.x;
    if (i >= E) return;
    int d = dst[i];
    int pos = atomicAdd(&g_cnt[d], 1);
    if (pos < PAD) g_csr[(size_t)d * PAD + pos] = src[i];
}

__global__ void dinv_kernel() {
    int i = blockIdx.x * blockDim.x + threadIdx.x;
    if (i < NN) g_dinv[i] = rsqrtf(1.0f + (float)g_cnt[i]);
}

// ---------------------------------------------------------------------------
// tf32 tensor-core GEMM: C = A[M x K] @ B[K x 128]
// Epilogue scales row r by g_dinv[r] and writes g_xws.
// CTA tile 128x128, BK=32. 8 warps (4m x 2n), warp tile 32x64.
// mma.sync.aligned.m16n8k8.row.col.f32.tf32.tf32.f32
// ---------------------------------------------------------------------------
__device__ __forceinline__ uint32_t f2tf32(float f) {
    uint32_t r;
    asm("cvt.rna.tf32.f32 %0, %1;" : "=r"(r) : "f"(f));
    return r;
}

template<int K, bool USE_H1>
__global__ void __launch_bounds__(256) mma_gemm_kernel(const float* __restrict__ A,
                                                       const float* __restrict__ B,
                                                       int M)
{
    constexpr int BM = 128, BK = 32;
    constexpr int ASTR = BK + 4;    // 36: A frag banks (4*lr + lc) conflict-free
    constexpr int BSTR = HD + 8;    // 136: B frag banks (8*lc + lr) conflict-free
    __shared__ float As[BM * ASTR];     // [m][k]  18.4KB
    __shared__ float Bs[BK * BSTR];     // [k][n]  17.4KB
    const float* Ap = USE_H1 ? (const float*)g_h1 : A;

    const int tid  = threadIdx.x;
    const int wid  = tid >> 5;
    const int lane = tid & 31;
    const int row0 = blockIdx.x * BM;
    const int wm   = (wid & 3) * 32;    // warp m offset in tile
    const int wn   = (wid >> 2) * 64;   // warp n offset in tile
    const int lr   = lane >> 2;         // 0..7
    const int lc   = lane & 3;          // 0..3

    float acc[2][8][4];
    #pragma unroll
    for (int mt = 0; mt < 2; mt++)
        #pragma unroll
        for (int nt = 0; nt < 8; nt++)
            #pragma unroll
            for (int i = 0; i < 4; i++) acc[mt][nt][i] = 0.0f;

    for (int k0 = 0; k0 < K; k0 += BK) {
        // ---- load A tile (128x32) : 1024 float4, direct copy, cvt->tf32 ----
        #pragma unroll
        for (int i = 0; i < 4; i++) {
            int idx = tid + i * 256;          // 0..1023
            int r   = idx >> 3;               // 0..127
            int k4  = (idx & 7) << 2;         // 0,4,..28
            float4 v = make_float4(0.f, 0.f, 0.f, 0.f);
            if (row0 + r < M)
                v = *(const float4*)(Ap + (size_t)(row0 + r) * K + k0 + k4);
            float4 c;
            c.x = __uint_as_float(f2tf32(v.x));
            c.y = __uint_as_float(f2tf32(v.y));
            c.z = __uint_as_float(f2tf32(v.z));
            c.w = __uint_as_float(f2tf32(v.w));
            *(float4*)&As[r * ASTR + k4] = c;
        }
        // ---- load B tile (32x128) : 1024 float4, direct copy, cvt->tf32 ----
        #pragma unroll
        for (int i = 0; i < 4; i++) {
            int idx = tid + i * 256;
            int k   = idx >> 5;               // 0..31
            int n4  = (idx & 31) << 2;        // 0..124
            float4 v = *(const float4*)(B + (size_t)(k0 + k) * HD + n4);
            float4 c;
            c.x = __uint_as_float(f2tf32(v.x));
            c.y = __uint_as_float(f2tf32(v.y));
            c.z = __uint_as_float(f2tf32(v.z));
            c.w = __uint_as_float(f2tf32(v.w));
            *(float4*)&Bs[k * BSTR + n4] = c;
        }
        __syncthreads();

        // ---- mma over 4 k-steps of 8 ----
        #pragma unroll
        for (int ks = 0; ks < 4; ks++) {
            int kb = ks * 8;
            uint32_t a[2][4];
            #pragma unroll
            for (int mt = 0; mt < 2; mt++) {
                int m = wm + mt * 16;
                a[mt][0] = __float_as_uint(As[(m + lr)     * ASTR + kb + lc]);
                a[mt][1] = __float_as_uint(As[(m + lr + 8) * ASTR + kb + lc]);
                a[mt][2] = __float_as_uint(As[(m + lr)     * ASTR + kb + lc + 4]);
                a[mt][3] = __float_as_uint(As[(m + lr + 8) * ASTR + kb + lc + 4]);
            }
            uint32_t b[8][2];
            #pragma unroll
            for (int nt = 0; nt < 8; nt++) {
                int n = wn + nt * 8;
                b[nt][0] = __float_as_uint(Bs[(kb + lc)     * BSTR + n + lr]);
                b[nt][1] = __float_as_uint(Bs[(kb + lc + 4) * BSTR + n + lr]);
            }
            #pragma unroll
            for (int mt = 0; mt < 2; mt++)
                #pragma unroll
                for (int nt = 0; nt < 8; nt++) {
                    asm volatile(
                        "mma.sync.aligned.m16n8k8.row.col.f32.tf32.tf32.f32 "
                        "{%0,%1,%2,%3}, {%4,%5,%6,%7}, {%8,%9}, {%0,%1,%2,%3};"
                        : "+f"(acc[mt][nt][0]), "+f"(acc[mt][nt][1]),
                          "+f"(acc[mt][nt][2]), "+f"(acc[mt][nt][3])
                        : "r"(a[mt][0]), "r"(a[mt][1]), "r"(a[mt][2]), "r"(a[mt][3]),
                          "r"(b[nt][0]), "r"(b[nt][1]));
                }
        }
        __syncthreads();
    }

    // ---- epilogue: scale by dinv, write g_xws ----
    #pragma unroll
    for (int mt = 0; mt < 2; mt++) {
        int r1 = row0 + wm + mt * 16 + lr;
        int r2 = r1 + 8;
        float s1 = (r1 < M) ? g_dinv[r1] : 0.f;
        float s2 = (r2 < M) ? g_dinv[r2] : 0.f;
        #pragma unroll
        for (int nt = 0; nt < 8; nt++) {
            int c = wn + nt * 8 + lc * 2;
            if (r1 < M) {
                float2 o = make_float2(acc[mt][nt][0] * s1, acc[mt][nt][1] * s1);
                *(float2*)(g_xws + (size_t)r1 * HD + c) = o;
            }
            if (r2 < M) {
                float2 o = make_float2(acc[mt][nt][2] * s2, acc[mt][nt][3] * s2);
                *(float2*)(g_xws + (size_t)r2 * HD + c) = o;
            }
        }
    }
}

// ---------------------------------------------------------------------------
// agg1: warp per node. sum = xws[n] + sum_{e} xws[csr[n][e]]
//       h1 = relu(dinv[n]*sum + b1)
// ---------------------------------------------------------------------------
__global__ void __launch_bounds__(256) agg1_kernel(const float* __restrict__ b1) {
    int n = (int)((blockIdx.x * 256u + threadIdx.x) >> 5);
    if (n >= NN) return;
    int lane = threadIdx.x & 31;
    int cnt = g_cnt[n];
    const int* lst = g_csr + (size_t)n * PAD;

    float4 sum = *(const float4*)(g_xws + (size_t)n * HD + lane * 4);  // self loop

    int e = 0;
    for (; e + 2 <= cnt; e += 2) {
        int s0 = __ldg(&lst[e]);
        int s1 = __ldg(&lst[e + 1]);
        float4 v0 = *(const float4*)(g_xws + (size_t)s0 * HD + lane * 4);
        float4 v1 = *(const float4*)(g_xws + (size_t)s1 * HD + lane * 4);
        sum.x += v0.x + v1.x;  sum.y += v0.y + v1.y;
        sum.z += v0.z + v1.z;  sum.w += v0.w + v1.w;
    }
    if (e < cnt) {
        int s0 = __ldg(&lst[e]);
        float4 v0 = *(const float4*)(g_xws + (size_t)s0 * HD + lane * 4);
        sum.x += v0.x;  sum.y += v0.y;  sum.z += v0.z;  sum.w += v0.w;
    }

    float s = g_dinv[n];
    float4 b = ((const float4*)b1)[lane];
    float4 h;
    h.x = fmaxf(fmaf(sum.x, s, b.x), 0.f);
    h.y = fmaxf(fmaf(sum.y, s, b.y), 0.f);
    h.z = fmaxf(fmaf(sum.z, s, b.z), 0.f);
    h.w = fmaxf(fmaf(sum.w, s, b.w), 0.f);
    *(float4*)(g_h1 + (size_t)n * HD + lane * 4) = h;
}

// ---------------------------------------------------------------------------
// agg2 + output: warp per node.
// ---------------------------------------------------------------------------
__global__ void __launch_bounds__(256) agg2out_kernel(const float* __restrict__ hnode,
                                                      const float* __restrict__ b2,
                                                      const float* __restrict__ Wc,
                                                      const float* __restrict__ bc,
                                                      const float* __restrict__ Wf,
                                                      const float* __restrict__ bf,
                                                      float* __restrict__ out)
{
    int n = (int)((blockIdx.x * 256u + threadIdx.x) >> 5);
    if (n >= NN) return;
    int lane = threadIdx.x & 31;
    int cnt = g_cnt[n];
    const int* lst = g_csr + (size_t)n * PAD;

    float4 sum = *(const float4*)(g_xws + (size_t)n * HD + lane * 4);  // self loop

    int e = 0;
    for (; e + 2 <= cnt; e += 2) {
        int s0 = __ldg(&lst[e]);
        int s1 = __ldg(&lst[e + 1]);
        float4 v0 = *(const float4*)(g_xws + (size_t)s0 * HD + lane * 4);
        float4 v1 = *(const float4*)(g_xws + (size_t)s1 * HD + lane * 4);
        sum.x += v0.x + v1.x;  sum.y += v0.y + v1.y;
        sum.z += v0.z + v1.z;  sum.w += v0.w + v1.w;
    }
    if (e < cnt) {
        int s0 = __ldg(&lst[e]);
        float4 v0 = *(const float4*)(g_xws + (size_t)s0 * HD + lane * 4);
        sum.x += v0.x;  sum.y += v0.y;  sum.z += v0.z;  sum.w += v0.w;
    }

    float s     = g_dinv[n];
    float alpha = hnode[n];
    float beta  = 1.0f - alpha;
    float4 bv   = ((const float4*)b2)[lane];
    float4 h1v  = *(const float4*)(g_h1 + (size_t)n * HD + lane * 4);

    float4 h2, ha;
    h2.x = fmaxf(fmaf(sum.x, s, bv.x), 0.f);
    h2.y = fmaxf(fmaf(sum.y, s, bv.y), 0.f);
    h2.z = fmaxf(fmaf(sum.z, s, bv.z), 0.f);
    h2.w = fmaxf(fmaf(sum.w, s, bv.w), 0.f);
    ha.x = alpha * h2.x + beta * h1v.x;
    ha.y = alpha * h2.y + beta * h1v.y;
    ha.z = alpha * h2.z + beta * h1v.z;
    ha.w = alpha * h2.w + beta * h1v.w;

    float4 wc0 = *(const float4*)(Wc + lane * 8);
    float4 wc1 = *(const float4*)(Wc + lane * 8 + 4);
    float4 wf0 = *(const float4*)(Wf + lane * 8);
    float4 wf1 = *(const float4*)(Wf + lane * 8 + 4);

    float c0 = h1v.x * wc0.x + h1v.y * wc0.z + h1v.z * wc1.x + h1v.w * wc1.z;
    float c1 = h1v.x * wc0.y + h1v.y * wc0.w + h1v.z * wc1.y + h1v.w * wc1.w;
    float f0 = ha.x * wf0.x + ha.y * wf0.z + ha.z * wf1.x + ha.w * wf1.z;
    float f1 = ha.x * wf0.y + ha.y * wf0.w + ha.z * wf1.y + ha.w * wf1.w;

    #pragma unroll
    for (int off = 16; off > 0; off >>= 1) {
        c0 += __shfl_xor_sync(0xFFFFFFFFu, c0, off);
        c1 += __shfl_xor_sync(0xFFFFFFFFu, c1, off);
        f0 += __shfl_xor_sync(0xFFFFFFFFu, f0, off);
        f1 += __shfl_xor_sync(0xFFFFFFFFu, f1, off);
    }
    if (lane == 0) {
        out[2 * (size_t)n + 0] = 0.5f * (c0 + bc[0]) + 0.5f * (f0 + bf[0]);
        out[2 * (size_t)n + 1] = 0.5f * (c1 + bc[1]) + 0.5f * (f1 + bf[1]);
    }
}

// ---------------------------------------------------------------------------
extern "C" void kernel_launch(void* const* d_in, const int* in_sizes, int n_in,
                              void* d_out, int out_size)
{
    const float* x     = (const float*)d_in[0];
    const int*   ei    = (const int*)d_in[1];     // int32 (jax x64 disabled)
    const float* hnode = (const float*)d_in[2];
    const float* W1    = (const float*)d_in[3];
    const float* b1    = (const float*)d_in[4];
    const float* W2    = (const float*)d_in[5];
    const float* b2    = (const float*)d_in[6];
    const float* Wc    = (const float*)d_in[7];
    const float* bc    = (const float*)d_in[8];
    const float* Wf    = (const float*)d_in[9];
    const float* bf    = (const float*)d_in[10];
    float* out = (float*)d_out;

    int E = in_sizes[1] / 2;
    const int* src = ei;
    const int* dst = ei + E;

    // CSR build + normalization
    zero_cnt_kernel<<<(NN + 255) / 256, 256>>>();
    csr_fill_kernel<<<(E + 255) / 256, 256>>>(src, dst, E);
    dinv_kernel<<<(NN + 255) / 256, 256>>>();

    // Conv1
    mma_gemm_kernel<IND, false><<<(NN + 127) / 128, 256>>>(x, W1, NN);
    agg1_kernel<<<((size_t)NN * 32 + 255) / 256, 256>>>(b1);

    // Conv2 + fused blend/heads/output
    mma_gemm_kernel<HD, true><<<(NN + 127) / 128, 256>>>(nullptr, W2, NN);
    agg2out_kernel<<<((size_t)NN * 32 + 255) / 256, 256>>>(hnode, b2, Wc, bc, Wf, bf, out);
}

// round 7
// speedup vs baseline: 3.4819x; 1.1744x over previous
#include <cuda_runtime.h>
#include <cuda_fp16.h>
#include <cstdint>

#define NN 100000
#define IND 256
#define HD 128
#define PAD 128          // max in-degree capacity per node (Poisson(16) -> max ~45)

// Scratch (static device globals — allocation-free per harness rules)
__device__ int    g_cnt[NN];                    // in-degree (excl self loop)
__device__ float  g_dinv[NN];
__device__ int    g_csr[(size_t)NN * PAD];      // src lists bucketed by dst
__device__ __half g_xws[(size_t)NN * HD];       // (A@W)*dinv, fp16 (gather source)
__device__ float  g_h1[(size_t)NN * HD];        // relu output of conv1 (fp32)
__device__ float  g_bt[IND * HD];               // tf32-prerounded B (max 256x128)

// ---------------------------------------------------------------------------
__global__ void zero_cnt_kernel() {
    int i = blockIdx.x * blockDim.x + threadIdx.x;
    if (i < NN) g_cnt[i] = 0;
}

__global__ void csr_fill_kernel(const int* __restrict__ src,
                                const int* __restrict__ dst, int E) {
    int i = blockIdx.x * blockDim.x + threadIdx.x;
    if (i >= E) return;
    int d = dst[i];
    int pos = atomicAdd(&g_cnt[d], 1);
    if (pos < PAD) g_csr[(size_t)d * PAD + pos] = src[i];
}

__global__ void dinv_kernel() {
    int i = blockIdx.x * blockDim.x + threadIdx.x;
    if (i < NN) g_dinv[i] = rsqrtf(1.0f + (float)g_cnt[i]);
}

// ---------------------------------------------------------------------------
__device__ __forceinline__ uint32_t f2tf32(float f) {
    uint32_t r;
    asm("cvt.rna.tf32.f32 %0, %1;" : "=r"(r) : "f"(f));
    return r;
}

// Pre-round B into g_bt (round-to-nearest tf32; avoids RZ truncation bias).
__global__ void cvtB_kernel(const float* __restrict__ B, int n) {
    int i = blockIdx.x * blockDim.x + threadIdx.x;
    if (i < n) g_bt[i] = __uint_as_float(f2tf32(B[i]));
}

__device__ __forceinline__ void cp16(uint32_t saddr, const void* g, int sz) {
    asm volatile("cp.async.ca.shared.global [%0], [%1], 16, %2;"
                 :: "r"(saddr), "l"(g), "r"(sz));
}

// ---------------------------------------------------------------------------
// tf32 tensor-core GEMM, 2-stage cp.async pipeline.
// C = A[M x K] @ B[K x 128]; epilogue scales row by dinv, writes fp16 g_xws.
// CTA 128x128, BK=32, 8 warps (4m x 2n), warp tile 32x64.
// ---------------------------------------------------------------------------
template<int K, bool USE_H1>
__global__ void __launch_bounds__(256) mma_gemm_kernel(const float* __restrict__ A,
                                                       int M)
{
    constexpr int BM = 128, BK = 32;
    constexpr int ASTR = BK + 4;      // 36 floats (144B, 16B-aligned rows)
    constexpr int BSTR = HD + 8;      // 136 floats (544B)
    constexpr int ASZ  = BM * ASTR;   // 4608 floats
    constexpr int BSZ  = BK * BSTR;   // 4352 floats
    constexpr int STG  = ASZ + BSZ;   // 8960 floats per stage
    constexpr int TILES = K / BK;
    extern __shared__ float smem[];

    const float* Ap = USE_H1 ? (const float*)g_h1 : A;
    const int tid  = threadIdx.x;
    const int wid  = tid >> 5;
    const int lane = tid & 31;
    const int row0 = blockIdx.x * BM;
    const int wm   = (wid & 3) * 32;
    const int wn   = (wid >> 2) * 64;
    const int lr   = lane >> 2;
    const int lc   = lane & 3;

    uint32_t sbase;
    {
        uint64_t tmp = (uint64_t)__cvta_generic_to_shared(smem);
        sbase = (uint32_t)tmp;
    }

    float acc[2][8][4];
    #pragma unroll
    for (int mt = 0; mt < 2; mt++)
        #pragma unroll
        for (int nt = 0; nt < 8; nt++)
            #pragma unroll
            for (int i = 0; i < 4; i++) acc[mt][nt][i] = 0.0f;

    auto load_tile = [&](int t, int stage) {
        uint32_t as = sbase + (uint32_t)(stage * STG) * 4u;
        uint32_t bs = as + (uint32_t)ASZ * 4u;
        #pragma unroll
        for (int i = 0; i < 4; i++) {
            int idx = tid + i * 256;
            int r   = idx >> 3;
            int k4  = (idx & 7) << 2;
            int gr  = row0 + r;
            int sz  = (gr < M) ? 16 : 0;
            int grc = (gr < M) ? gr : (M - 1);
            cp16(as + (uint32_t)(r * ASTR + k4) * 4u,
                 Ap + (size_t)grc * K + t * BK + k4, sz);
        }
        #pragma unroll
        for (int i = 0; i < 4; i++) {
            int idx = tid + i * 256;
            int k   = idx >> 5;
            int n4  = (idx & 31) << 2;
            cp16(bs + (uint32_t)(k * BSTR + n4) * 4u,
                 g_bt + (size_t)(t * BK + k) * HD + n4, 16);
        }
    };

    load_tile(0, 0);
    asm volatile("cp.async.commit_group;");

    for (int t = 0; t < TILES; t++) {
        if (t + 1 < TILES) {
            load_tile(t + 1, (t + 1) & 1);
            asm volatile("cp.async.commit_group;");
            asm volatile("cp.async.wait_group 1;");
        } else {
            asm volatile("cp.async.wait_group 0;");
        }
        __syncthreads();

        const float* As = smem + (t & 1) * STG;
        const float* Bs = As + ASZ;

        #pragma unroll
        for (int ks = 0; ks < 4; ks++) {
            int kb = ks * 8;
            uint32_t a[2][4];
            #pragma unroll
            for (int mt = 0; mt < 2; mt++) {
                int m = wm + mt * 16;
                a[mt][0] = f2tf32(As[(m + lr)     * ASTR + kb + lc]);
                a[mt][1] = f2tf32(As[(m + lr + 8) * ASTR + kb + lc]);
                a[mt][2] = f2tf32(As[(m + lr)     * ASTR + kb + lc + 4]);
                a[mt][3] = f2tf32(As[(m + lr + 8) * ASTR + kb + lc + 4]);
            }
            uint32_t b[8][2];
            #pragma unroll
            for (int nt = 0; nt < 8; nt++) {
                int n = wn + nt * 8;
                b[nt][0] = __float_as_uint(Bs[(kb + lc)     * BSTR + n + lr]);
                b[nt][1] = __float_as_uint(Bs[(kb + lc + 4) * BSTR + n + lr]);
            }
            #pragma unroll
            for (int mt = 0; mt < 2; mt++)
                #pragma unroll
                for (int nt = 0; nt < 8; nt++) {
                    asm volatile(
                        "mma.sync.aligned.m16n8k8.row.col.f32.tf32.tf32.f32 "
                        "{%0,%1,%2,%3}, {%4,%5,%6,%7}, {%8,%9}, {%0,%1,%2,%3};"
                        : "+f"(acc[mt][nt][0]), "+f"(acc[mt][nt][1]),
                          "+f"(acc[mt][nt][2]), "+f"(acc[mt][nt][3])
                        : "r"(a[mt][0]), "r"(a[mt][1]), "r"(a[mt][2]), "r"(a[mt][3]),
                          "r"(b[nt][0]), "r"(b[nt][1]));
                }
        }
        __syncthreads();
    }

    // ---- epilogue: scale by dinv, write fp16 g_xws ----
    #pragma unroll
    for (int mt = 0; mt < 2; mt++) {
        int r1 = row0 + wm + mt * 16 + lr;
        int r2 = r1 + 8;
        float s1 = (r1 < M) ? g_dinv[r1] : 0.f;
        float s2 = (r2 < M) ? g_dinv[r2] : 0.f;
        #pragma unroll
        for (int nt = 0; nt < 8; nt++) {
            int c = wn + nt * 8 + lc * 2;
            if (r1 < M)
                *(__half2*)(g_xws + (size_t)r1 * HD + c) =
                    __floats2half2_rn(acc[mt][nt][0] * s1, acc[mt][nt][1] * s1);
            if (r2 < M)
                *(__half2*)(g_xws + (size_t)r2 * HD + c) =
                    __floats2half2_rn(acc[mt][nt][2] * s2, acc[mt][nt][3] * s2);
        }
    }
}

// ---------------------------------------------------------------------------
// fp16 gather helper: lane owns features [4L, 4L+4) = 8 bytes
// ---------------------------------------------------------------------------
__device__ __forceinline__ void add_row(float4& sum, int s, int lane) {
    uint2 raw = *(const uint2*)(g_xws + (size_t)s * HD + lane * 4);
    float2 p0 = __half22float2(*(const __half2*)&raw.x);
    float2 p1 = __half22float2(*(const __half2*)&raw.y);
    sum.x += p0.x;  sum.y += p0.y;  sum.z += p1.x;  sum.w += p1.y;
}

// ---------------------------------------------------------------------------
// agg1: warp per node. sum = xws[n] + sum_e xws[csr[n][e]]; h1 = relu(dinv*sum+b1)
// ---------------------------------------------------------------------------
__global__ void __launch_bounds__(256) agg1_kernel(const float* __restrict__ b1) {
    int n = (int)((blockIdx.x * 256u + threadIdx.x) >> 5);
    if (n >= NN) return;
    int lane = threadIdx.x & 31;
    int cnt = g_cnt[n];
    const int* lst = g_csr + (size_t)n * PAD;

    float4 sum = make_float4(0.f, 0.f, 0.f, 0.f);
    add_row(sum, n, lane);                      // self loop

    int e = 0;
    for (; e + 4 <= cnt; e += 4) {
        int s0 = __ldg(&lst[e]);
        int s1 = __ldg(&lst[e + 1]);
        int s2 = __ldg(&lst[e + 2]);
        int s3 = __ldg(&lst[e + 3]);
        add_row(sum, s0, lane);
        add_row(sum, s1, lane);
        add_row(sum, s2, lane);
        add_row(sum, s3, lane);
    }
    for (; e < cnt; e++) add_row(sum, __ldg(&lst[e]), lane);

    float s = g_dinv[n];
    float4 b = ((const float4*)b1)[lane];
    float4 h;
    h.x = fmaxf(fmaf(sum.x, s, b.x), 0.f);
    h.y = fmaxf(fmaf(sum.y, s, b.y), 0.f);
    h.z = fmaxf(fmaf(sum.z, s, b.z), 0.f);
    h.w = fmaxf(fmaf(sum.w, s, b.w), 0.f);
    *(float4*)(g_h1 + (size_t)n * HD + lane * 4) = h;
}

// ---------------------------------------------------------------------------
// agg2 + output: warp per node.
// ---------------------------------------------------------------------------
__global__ void __launch_bounds__(256) agg2out_kernel(const float* __restrict__ hnode,
                                                      const float* __restrict__ b2,
                                                      const float* __restrict__ Wc,
                                                      const float* __restrict__ bc,
                                                      const float* __restrict__ Wf,
                                                      const float* __restrict__ bf,
                                                      float* __restrict__ out)
{
    int n = (int)((blockIdx.x * 256u + threadIdx.x) >> 5);
    if (n >= NN) return;
    int lane = threadIdx.x & 31;
    int cnt = g_cnt[n];
    const int* lst = g_csr + (size_t)n * PAD;

    float4 sum = make_float4(0.f, 0.f, 0.f, 0.f);
    add_row(sum, n, lane);                      // self loop

    int e = 0;
    for (; e + 4 <= cnt; e += 4) {
        int s0 = __ldg(&lst[e]);
        int s1 = __ldg(&lst[e + 1]);
        int s2 = __ldg(&lst[e + 2]);
        int s3 = __ldg(&lst[e + 3]);
        add_row(sum, s0, lane);
        add_row(sum, s1, lane);
        add_row(sum, s2, lane);
        add_row(sum, s3, lane);
    }
    for (; e < cnt; e++) add_row(sum, __ldg(&lst[e]), lane);

    float s     = g_dinv[n];
    float alpha = hnode[n];
    float beta  = 1.0f - alpha;
    float4 bv   = ((const float4*)b2)[lane];
    float4 h1v  = *(const float4*)(g_h1 + (size_t)n * HD + lane * 4);

    float4 h2, ha;
    h2.x = fmaxf(fmaf(sum.x, s, bv.x), 0.f);
    h2.y = fmaxf(fmaf(sum.y, s, bv.y), 0.f);
    h2.z = fmaxf(fmaf(sum.z, s, bv.z), 0.f);
    h2.w = fmaxf(fmaf(sum.w, s, bv.w), 0.f);
    ha.x = alpha * h2.x + beta * h1v.x;
    ha.y = alpha * h2.y + beta * h1v.y;
    ha.z = alpha * h2.z + beta * h1v.z;
    ha.w = alpha * h2.w + beta * h1v.w;

    float4 wc0 = *(const float4*)(Wc + lane * 8);
    float4 wc1 = *(const float4*)(Wc + lane * 8 + 4);
    float4 wf0 = *(const float4*)(Wf + lane * 8);
    float4 wf1 = *(const float4*)(Wf + lane * 8 + 4);

    float c0 = h1v.x * wc0.x + h1v.y * wc0.z + h1v.z * wc1.x + h1v.w * wc1.z;
    float c1 = h1v.x * wc0.y + h1v.y * wc0.w + h1v.z * wc1.y + h1v.w * wc1.w;
    float f0 = ha.x * wf0.x + ha.y * wf0.z + ha.z * wf1.x + ha.w * wf1.z;
    float f1 = ha.x * wf0.y + ha.y * wf0.w + ha.z * wf1.y + ha.w * wf1.w;

    #pragma unroll
    for (int off = 16; off > 0; off >>= 1) {
        c0 += __shfl_xor_sync(0xFFFFFFFFu, c0, off);
        c1 += __shfl_xor_sync(0xFFFFFFFFu, c1, off);
        f0 += __shfl_xor_sync(0xFFFFFFFFu, f0, off);
        f1 += __shfl_xor_sync(0xFFFFFFFFu, f1, off);
    }
    if (lane == 0) {
        out[2 * (size_t)n + 0] = 0.5f * (c0 + bc[0]) + 0.5f * (f0 + bf[0]);
        out[2 * (size_t)n + 1] = 0.5f * (c1 + bc[1]) + 0.5f * (f1 + bf[1]);
    }
}

// ---------------------------------------------------------------------------
extern "C" void kernel_launch(void* const* d_in, const int* in_sizes, int n_in,
                              void* d_out, int out_size)
{
    const float* x     = (const float*)d_in[0];
    const int*   ei    = (const int*)d_in[1];     // int32 (jax x64 disabled)
    const float* hnode = (const float*)d_in[2];
    const float* W1    = (const float*)d_in[3];
    const float* b1    = (const float*)d_in[4];
    const float* W2    = (const float*)d_in[5];
    const float* b2    = (const float*)d_in[6];
    const float* Wc    = (const float*)d_in[7];
    const float* bc    = (const float*)d_in[8];
    const float* Wf    = (const float*)d_in[9];
    const float* bf    = (const float*)d_in[10];
    float* out = (float*)d_out;

    int E = in_sizes[1] / 2;
    const int* src = ei;
    const int* dst = ei + E;

    // Dynamic smem for the pipelined GEMM (2 stages x 35840B = 71680B)
    constexpr int SMEM_BYTES = 2 * (128 * 36 + 32 * 136) * 4;
    cudaFuncSetAttribute(mma_gemm_kernel<IND, false>,
                         cudaFuncAttributeMaxDynamicSharedMemorySize, SMEM_BYTES);
    cudaFuncSetAttribute(mma_gemm_kernel<HD, true>,
                         cudaFuncAttributeMaxDynamicSharedMemorySize, SMEM_BYTES);

    // CSR build + normalization
    zero_cnt_kernel<<<(NN + 255) / 256, 256>>>();
    csr_fill_kernel<<<(E + 255) / 256, 256>>>(src, dst, E);
    dinv_kernel<<<(NN + 255) / 256, 256>>>();

    // Conv1
    cvtB_kernel<<<(IND * HD + 255) / 256, 256>>>(W1, IND * HD);
    mma_gemm_kernel<IND, false><<<(NN + 127) / 128, 256, SMEM_BYTES>>>(x, NN);
    agg1_kernel<<<((size_t)NN * 32 + 255) / 256, 256>>>(b1);

    // Conv2 + fused blend/heads/output
    cvtB_kernel<<<(HD * HD + 255) / 256, 256>>>(W2, HD * HD);
    mma_gemm_kernel<HD, true><<<(NN + 127) / 128, 256, SMEM_BYTES>>>(nullptr, NN);
    agg2out_kernel<<<((size_t)NN * 32 + 255) / 256, 256>>>(hnode, b2, Wc, bc, Wf, bf, out);
}